// round 2
// baseline (speedup 1.0000x reference)
#include <cuda_runtime.h>

#define SEQ_LEN   8192
#define HIDDEN    1024
#define NUM_SPANS 4096
#define MAX_W     32
#define H4        256                  // float4 per row
#define TP        16                   // starts per tile
#define NT        (SEQ_LEN / TP)       // 512 tiles
#define NROWS     (TP + MAX_W - 1)     // 47-row window per tile
#define CHUNK     8                    // rows per cp.async group
#define NCH       ((NROWS + CHUNK - 1) / CHUNK)   // 6
#define CAP       64                   // spans per processing round
#define LISTCAP   1024

__device__ float g_scores[SEQ_LEN];

// ---------------- Kernel A: per-position attention logits ----------------
__global__ void score_kernel(const float* __restrict__ emb,
                             const float* __restrict__ attn_w,
                             const float* __restrict__ attn_b) {
    int warp = (blockIdx.x * blockDim.x + threadIdx.x) >> 5;
    int lane = threadIdx.x & 31;
    if (warp >= SEQ_LEN) return;

    const float4* row = (const float4*)(emb) + (size_t)warp * H4;
    const float4* wv  = (const float4*)(attn_w);

    float acc = 0.0f;
#pragma unroll
    for (int j = 0; j < H4 / 32; j++) {
        float4 a = row[j * 32 + lane];
        float4 c = wv [j * 32 + lane];
        acc += a.x * c.x + a.y * c.y + a.z * c.z + a.w * c.w;
    }
#pragma unroll
    for (int off = 16; off; off >>= 1)
        acc += __shfl_xor_sync(0xffffffffu, acc, off);

    if (lane == 0) g_scores[warp] = acc + attn_b[0];
}

// ---------------- Kernel B: sequence-tiled span processing ----------------
__device__ __forceinline__ void cp_async16(void* dst_smem, const void* src) {
    unsigned saddr = (unsigned)__cvta_generic_to_shared(dst_smem);
    asm volatile("cp.async.cg.shared.global [%0], [%1], 16;\n"
                 :: "r"(saddr), "l"(src));
}
__device__ __forceinline__ void cp_commit() {
    asm volatile("cp.async.commit_group;\n");
}
__device__ __forceinline__ void cp_wait(int c) {   // allow (NCH-1-c) pending
    switch (c) {
        case 0: asm volatile("cp.async.wait_group 5;\n"); break;
        case 1: asm volatile("cp.async.wait_group 4;\n"); break;
        case 2: asm volatile("cp.async.wait_group 3;\n"); break;
        case 3: asm volatile("cp.async.wait_group 2;\n"); break;
        case 4: asm volatile("cp.async.wait_group 1;\n"); break;
        default: asm volatile("cp.async.wait_group 0;\n"); break;
    }
}

__global__ __launch_bounds__(256) void tile_kernel(
        const float* __restrict__ emb,
        const int*   __restrict__ starts,
        const int*   __restrict__ ends,
        float*       __restrict__ out) {
    extern __shared__ float4 srows[];            // NROWS * H4 float4 = 188 KB
    __shared__ float s_sc[NROWS];
    __shared__ float s_w[CAP][MAX_W];            // softmax weights per slot
    __shared__ int   s_idx[LISTCAP];
    __shared__ int   s_start[CAP], s_wid[CAP];
    __shared__ int   s_cnt;

    const int tid = threadIdx.x;                 // 256 == H4: one float4 col/thread
    const int t0  = blockIdx.x * TP;

    if (tid == 0) s_cnt = 0;
    __syncthreads();

    // ---- scan: which spans start in this tile? ----
    for (int j = tid; j < NUM_SPANS; j += 256) {
        int s = starts[j];
        if (s >= t0 && s < t0 + TP) {
            int p = atomicAdd(&s_cnt, 1);
            if (p < LISTCAP) s_idx[p] = j;
        }
    }
    // stage logits for the window
    for (int r = tid; r < NROWS; r += 256) {
        int g = t0 + r;
        s_sc[r] = (g < SEQ_LEN) ? g_scores[g] : -1e9f;
    }
    __syncthreads();

    const int cnt = min(s_cnt, LISTCAP);
    if (cnt == 0) return;

    // ---- issue all row-window loads as NCH cp.async groups ----
#pragma unroll
    for (int c = 0; c < NCH; c++) {
        int r0 = c * CHUNK;
        int r1 = min(NROWS, r0 + CHUNK);
        int n4 = (r1 - r0) * H4;
        for (int i = tid; i < n4; i += 256) {
            int r = r0 + (i >> 8);
            int col = i & 255;
            int g = t0 + r;
            if (g < SEQ_LEN)
                cp_async16(srows + r * H4 + col,
                           (const float4*)emb + (size_t)g * H4 + col);
        }
        cp_commit();
    }

    bool first = true;
    for (int base = 0; base < cnt; base += CAP) {
        const int n = min(CAP, cnt - base);

        // ---- softmax weights: one warp per slot (round-robin) ----
        {
            int wid = tid >> 5, lane = tid & 31;
            for (int slot = wid; slot < n; slot += 8) {
                int j = s_idx[base + slot];
                int s = starts[j];
                int W = ends[j] - s;             // width-1 in [0,31]
                float sc = (lane <= W) ? s_sc[s - t0 + lane] : -1e9f;
                float m = sc;
#pragma unroll
                for (int off = 16; off; off >>= 1)
                    m = fmaxf(m, __shfl_xor_sync(0xffffffffu, m, off));
                float p = __expf(sc - m);
                float sum = p;
#pragma unroll
                for (int off = 16; off; off >>= 1)
                    sum += __shfl_xor_sync(0xffffffffu, sum, off);
                s_w[slot][lane] = p / sum;
                if (lane == 0) { s_start[slot] = s - t0; s_wid[slot] = W; }
            }
        }
        __syncthreads();

        if (first) {
            // process spans as soon as their last row-chunk has landed
#pragma unroll
            for (int c = 0; c < NCH; c++) {
                cp_wait(c);
                __syncthreads();                 // make peers' async stores visible
                for (int slot = 0; slot < n; slot++) {
                    int s0 = s_start[slot], W = s_wid[slot];
                    if (((s0 + W) >> 3) != c) continue;
                    int j = s_idx[base + slot];
                    float4* o = (float4*)out + (size_t)j * (3 * H4);
                    float4 acc = make_float4(0.f, 0.f, 0.f, 0.f);
                    const float4* rp = srows + s0 * H4 + tid;
                    for (int r = 0; r <= W; r++) {
                        float4 v = rp[r * H4];
                        float wi = s_w[slot][r];
                        acc.x = fmaf(wi, v.x, acc.x);
                        acc.y = fmaf(wi, v.y, acc.y);
                        acc.z = fmaf(wi, v.z, acc.z);
                        acc.w = fmaf(wi, v.w, acc.w);
                        if (r == 0) o[tid]      = v;   // start_emb
                        if (r == W) o[H4 + tid] = v;   // end_emb
                    }
                    o[2 * H4 + tid] = acc;             // attn_out
                }
            }
            first = false;
        } else {
            // all rows already resident in smem
            for (int slot = 0; slot < n; slot++) {
                int s0 = s_start[slot], W = s_wid[slot];
                int j = s_idx[base + slot];
                float4* o = (float4*)out + (size_t)j * (3 * H4);
                float4 acc = make_float4(0.f, 0.f, 0.f, 0.f);
                const float4* rp = srows + s0 * H4 + tid;
                for (int r = 0; r <= W; r++) {
                    float4 v = rp[r * H4];
                    float wi = s_w[slot][r];
                    acc.x = fmaf(wi, v.x, acc.x);
                    acc.y = fmaf(wi, v.y, acc.y);
                    acc.z = fmaf(wi, v.z, acc.z);
                    acc.w = fmaf(wi, v.w, acc.w);
                    if (r == 0) o[tid]      = v;
                    if (r == W) o[H4 + tid] = v;
                }
                o[2 * H4 + tid] = acc;
            }
        }
        __syncthreads();   // protect s_w/s_start before next round
    }
}

extern "C" void kernel_launch(void* const* d_in, const int* in_sizes, int n_in,
                              void* d_out, int out_size) {
    const float* emb    = (const float*)d_in[0];
    const int*   starts = (const int*)  d_in[1];
    const int*   ends   = (const int*)  d_in[2];
    const float* attn_w = (const float*)d_in[3];
    const float* attn_b = (const float*)d_in[4];
    float*       out    = (float*)d_out;

    static const size_t smem_rows = (size_t)NROWS * HIDDEN * sizeof(float); // 188 KB
    cudaFuncSetAttribute(tile_kernel,
                         cudaFuncAttributeMaxDynamicSharedMemorySize,
                         (int)smem_rows);

    score_kernel<<<SEQ_LEN / 8, 256>>>(emb, attn_w, attn_b);
    tile_kernel<<<NT, 256, smem_rows>>>(emb, starts, ends, out);
}

// round 3
// speedup vs baseline: 1.1658x; 1.1658x over previous
#include <cuda_runtime.h>

#define SEQ_LEN   8192
#define HIDDEN    1024
#define H4        256                 // float4 per full row
#define NUM_SPANS 4096
#define MAX_W     32
#define TP        32                  // starts per tile
#define NTILES    (SEQ_LEN / TP)      // 256
#define NROWS     (TP + MAX_W - 1)    // 63-row window
#define HQ        64                  // float4 per quarter-row
#define NQ        4                   // hidden quarters
#define BINCAP    96
#define RCAP      32                  // slots per weight round

__device__ float g_scores[SEQ_LEN];
__device__ int   g_bincnt[NTILES];
__device__ int   g_bins[NTILES][BINCAP];

// ---------------- Kernel A: per-position logits (+ zero bin counters) ------
__global__ void score_kernel(const float* __restrict__ emb,
                             const float* __restrict__ attn_w,
                             const float* __restrict__ attn_b) {
    int gtid = blockIdx.x * blockDim.x + threadIdx.x;
    if (gtid < NTILES) g_bincnt[gtid] = 0;

    int warp = gtid >> 5;
    int lane = threadIdx.x & 31;
    if (warp >= SEQ_LEN) return;

    const float4* row = (const float4*)(emb) + (size_t)warp * H4;
    const float4* wv  = (const float4*)(attn_w);

    float acc = 0.0f;
#pragma unroll
    for (int j = 0; j < H4 / 32; j++) {
        float4 a = row[j * 32 + lane];
        float4 c = wv [j * 32 + lane];
        acc += a.x * c.x + a.y * c.y + a.z * c.z + a.w * c.w;
    }
#pragma unroll
    for (int off = 16; off; off >>= 1)
        acc += __shfl_xor_sync(0xffffffffu, acc, off);

    if (lane == 0) g_scores[warp] = acc + attn_b[0];
}

// ---------------- Kernel B: bin spans by start tile ------------------------
__global__ void bin_kernel(const int* __restrict__ starts) {
    int j = blockIdx.x * blockDim.x + threadIdx.x;
    if (j >= NUM_SPANS) return;
    int b = starts[j] / TP;
    int p = atomicAdd(&g_bincnt[b], 1);
    if (p < BINCAP) g_bins[b][p] = j;
}

// ---------------- Kernel C: tiled span processing --------------------------
__device__ __forceinline__ void cp_async16(void* dst_smem, const void* src) {
    unsigned saddr = (unsigned)__cvta_generic_to_shared(dst_smem);
    asm volatile("cp.async.cg.shared.global [%0], [%1], 16;\n"
                 :: "r"(saddr), "l"(src));
}

__global__ __launch_bounds__(256) void tile_kernel(
        const float* __restrict__ emb,
        const int*   __restrict__ starts,
        const int*   __restrict__ ends,
        float*       __restrict__ out) {
    extern __shared__ float4 srows[];            // NROWS * HQ float4 = 63 KB
    __shared__ float s_sc[NROWS];
    __shared__ float s_w[RCAP][MAX_W];
    __shared__ int   s_idx[BINCAP];
    __shared__ int   s_s0[RCAP], s_wd[RCAP];
    __shared__ int   s_cnt;

    const int tid  = threadIdx.x;
    const int tile = blockIdx.x >> 2;
    const int q    = blockIdx.x & 3;
    const int t0   = tile * TP;
    const int h0   = q * HQ;                     // float4 column offset

    if (tid == 0) s_cnt = min(g_bincnt[tile], BINCAP);
    __syncthreads();
    const int cnt = s_cnt;
    if (cnt == 0) return;

    // ---- issue window fill: 63 rows x 64 float4 (quarter of each row) ----
    {
        const float4* eb = (const float4*)emb;
        for (int i = tid; i < NROWS * HQ; i += 256) {
            int r = i >> 6, col = i & 63;
            int g = t0 + r;
            if (g < SEQ_LEN)
                cp_async16(srows + i, eb + (size_t)g * H4 + h0 + col);
        }
        asm volatile("cp.async.commit_group;\n");
    }

    // ---- stage span list + logits (overlaps with fill) ----
    for (int i = tid; i < cnt; i += 256) s_idx[i] = g_bins[tile][i];
    for (int r = tid; r < NROWS; r += 256) {
        int g = t0 + r;
        s_sc[r] = (g < SEQ_LEN) ? g_scores[g] : -1e9f;
    }
    __syncthreads();

    const int sgrp = tid >> 6;                   // 0..3: concurrent slot group
    const int col  = tid & 63;

    for (int base = 0; base < cnt; base += RCAP) {
        const int n = min(RCAP, cnt - base);

        // ---- softmax weights: one warp per slot ----
        {
            int wid = tid >> 5, lane = tid & 31;
            for (int slot = wid; slot < n; slot += 8) {
                int j = s_idx[base + slot];
                int s = starts[j];
                int W = ends[j] - s;             // width-1 in [0,31]
                float sc = (lane <= W) ? s_sc[s - t0 + lane] : -1e9f;
                float m = sc;
#pragma unroll
                for (int off = 16; off; off >>= 1)
                    m = fmaxf(m, __shfl_xor_sync(0xffffffffu, m, off));
                float p = __expf(sc - m);
                float sum = p;
#pragma unroll
                for (int off = 16; off; off >>= 1)
                    sum += __shfl_xor_sync(0xffffffffu, sum, off);
                s_w[slot][lane] = p / sum;
                if (lane == 0) { s_s0[slot] = s - t0; s_wd[slot] = W; }
            }
        }
        asm volatile("cp.async.wait_group 0;\n");
        __syncthreads();                          // weights + fill visible

        // ---- 4 slots processed concurrently (one 64-thread group each) ----
        for (int k = sgrp; k < n; k += NQ) {
            int s0 = s_s0[k], W = s_wd[k];
            int j  = s_idx[base + k];
            float4* o = (float4*)out + (size_t)j * (3 * H4) + h0 + col;
            const float4* rp = srows + s0 * HQ + col;
            float4 acc = make_float4(0.f, 0.f, 0.f, 0.f);
            for (int r = 0; r <= W; r++) {
                float4 v = rp[r * HQ];
                float wi = s_w[k][r];
                acc.x = fmaf(wi, v.x, acc.x);
                acc.y = fmaf(wi, v.y, acc.y);
                acc.z = fmaf(wi, v.z, acc.z);
                acc.w = fmaf(wi, v.w, acc.w);
                if (r == 0) o[0]  = v;            // start_emb
                if (r == W) o[H4] = v;            // end_emb
            }
            o[2 * H4] = acc;                      // attn_out
        }
        __syncthreads();                          // protect s_w before rewrite
    }
}

extern "C" void kernel_launch(void* const* d_in, const int* in_sizes, int n_in,
                              void* d_out, int out_size) {
    const float* emb    = (const float*)d_in[0];
    const int*   starts = (const int*)  d_in[1];
    const int*   ends   = (const int*)  d_in[2];
    const float* attn_w = (const float*)d_in[3];
    const float* attn_b = (const float*)d_in[4];
    float*       out    = (float*)d_out;

    static const int smem_rows = NROWS * HQ * sizeof(float4); // 64512 B
    cudaFuncSetAttribute(tile_kernel,
                         cudaFuncAttributeMaxDynamicSharedMemorySize,
                         smem_rows);

    score_kernel<<<SEQ_LEN / 8, 256>>>(emb, attn_w, attn_b);
    bin_kernel<<<NUM_SPANS / 256, 256>>>(starts);
    tile_kernel<<<NTILES * NQ, 256, smem_rows>>>(emb, starts, ends, out);
}

// round 4
// speedup vs baseline: 1.2712x; 1.0904x over previous
#include <cuda_runtime.h>

#define SEQ_LEN   8192
#define HIDDEN    1024
#define H4        256                 // float4 per row
#define NUM_SPANS 4096
#define MAX_W     32
#define SPB       8                   // sorted spans per CTA (one per warp)

__device__ float g_scores[SEQ_LEN];
__device__ int   g_cnt[SEQ_LEN];
__device__ int   g_off[SEQ_LEN];
__device__ int   g_sorted[NUM_SPANS];

// ---------------- Kernel A: per-position logits + zero histogram ----------
__global__ void score_kernel(const float* __restrict__ emb,
                             const float* __restrict__ attn_w,
                             const float* __restrict__ attn_b) {
    int gtid = blockIdx.x * blockDim.x + threadIdx.x;
    if (gtid < SEQ_LEN) g_cnt[gtid] = 0;

    int warp = gtid >> 5;
    int lane = threadIdx.x & 31;
    if (warp >= SEQ_LEN) return;

    const float4* row = (const float4*)(emb) + (size_t)warp * H4;
    const float4* wv  = (const float4*)(attn_w);

    float acc = 0.0f;
#pragma unroll
    for (int j = 0; j < H4 / 32; j++) {
        float4 a = row[j * 32 + lane];
        float4 c = wv [j * 32 + lane];
        acc += a.x * c.x + a.y * c.y + a.z * c.z + a.w * c.w;
    }
#pragma unroll
    for (int off = 16; off; off >>= 1)
        acc += __shfl_xor_sync(0xffffffffu, acc, off);

    if (lane == 0) g_scores[warp] = acc + attn_b[0];
}

// ---------------- Kernel B: histogram of starts ---------------------------
__global__ void hist_kernel(const int* __restrict__ starts) {
    int j = blockIdx.x * blockDim.x + threadIdx.x;
    if (j < NUM_SPANS) atomicAdd(&g_cnt[starts[j]], 1);
}

// ---------------- Kernel C: exclusive scan of 8192 counters (1 block) -----
__global__ __launch_bounds__(1024) void scan_kernel() {
    __shared__ int wsum[32];
    const int t = threadIdx.x;            // 0..1023, 8 elems each
    const int base = t * 8;

    int loc[8];
    int run = 0;
#pragma unroll
    for (int i = 0; i < 8; i++) { loc[i] = run; run += g_cnt[base + i]; }

    const int lane = t & 31, wid = t >> 5;
    int x = run;
#pragma unroll
    for (int off = 1; off < 32; off <<= 1) {
        int y = __shfl_up_sync(0xffffffffu, x, off);
        if (lane >= off) x += y;
    }
    if (lane == 31) wsum[wid] = x;
    __syncthreads();
    if (wid == 0) {
        int s = wsum[lane];
#pragma unroll
        for (int off = 1; off < 32; off <<= 1) {
            int y = __shfl_up_sync(0xffffffffu, s, off);
            if (lane >= off) s += y;
        }
        wsum[lane] = s;
    }
    __syncthreads();

    int excl = x - run + (wid ? wsum[wid - 1] : 0);
#pragma unroll
    for (int i = 0; i < 8; i++) g_off[base + i] = excl + loc[i];
}

// ---------------- Kernel D: scatter span ids into sorted order ------------
__global__ void scatter_kernel(const int* __restrict__ starts) {
    int j = blockIdx.x * blockDim.x + threadIdx.x;
    if (j >= NUM_SPANS) return;
    int p = atomicAdd(&g_off[starts[j]], 1);
    g_sorted[p] = j;
}

// ---------------- Kernel E: main — one warp per sorted span ---------------
__global__ __launch_bounds__(256) void span_main(
        const float* __restrict__ emb,
        const int*   __restrict__ starts,
        const int*   __restrict__ ends,
        float*       __restrict__ out) {
    __shared__ float s_w[SPB][MAX_W + 1];

    const int tid  = threadIdx.x;
    const int wid  = tid >> 5;
    const int lane = tid & 31;
    const int slot = blockIdx.x * SPB + wid;
    if (slot >= NUM_SPANS) return;

    const int j = g_sorted[slot];
    const int s = starts[j];
    const int W = ends[j] - s;            // width-1 in [0,31]

    // ---- per-warp masked softmax over precomputed logits ----
    {
        float sc = (lane <= W) ? g_scores[s + lane] : -1e9f;
        float m = sc;
#pragma unroll
        for (int off = 16; off; off >>= 1)
            m = fmaxf(m, __shfl_xor_sync(0xffffffffu, m, off));
        float p = __expf(sc - m);
        float sum = p;
#pragma unroll
        for (int off = 16; off; off >>= 1)
            sum += __shfl_xor_sync(0xffffffffu, sum, off);
        s_w[wid][lane] = p / sum;
    }
    __syncwarp();

    // ---- warp-level gather: lane covers 8 float4 columns ----
    const float4* base = (const float4*)(emb) + (size_t)s * H4 + lane;
    float4*       o    = (float4*)(out) + (size_t)j * (3 * H4) + lane;

    float4 acc[8];
#pragma unroll
    for (int c = 0; c < 8; c++) acc[c] = make_float4(0.f, 0.f, 0.f, 0.f);

    for (int r = 0; r <= W; r++) {
        const float wgt = s_w[wid][r];            // broadcast LDS
        const float4* rp = base + (size_t)r * H4;
        const bool first = (r == 0), last = (r == W);
#pragma unroll
        for (int c = 0; c < 8; c++) {
            float4 v = rp[c * 32];
            acc[c].x = fmaf(wgt, v.x, acc[c].x);
            acc[c].y = fmaf(wgt, v.y, acc[c].y);
            acc[c].z = fmaf(wgt, v.z, acc[c].z);
            acc[c].w = fmaf(wgt, v.w, acc[c].w);
            if (first) o[c * 32]      = v;        // start_emb
            if (last)  o[H4 + c * 32] = v;        // end_emb
        }
    }
#pragma unroll
    for (int c = 0; c < 8; c++) o[2 * H4 + c * 32] = acc[c];
}

extern "C" void kernel_launch(void* const* d_in, const int* in_sizes, int n_in,
                              void* d_out, int out_size) {
    const float* emb    = (const float*)d_in[0];
    const int*   starts = (const int*)  d_in[1];
    const int*   ends   = (const int*)  d_in[2];
    const float* attn_w = (const float*)d_in[3];
    const float* attn_b = (const float*)d_in[4];
    float*       out    = (float*)d_out;

    score_kernel<<<SEQ_LEN / 8, 256>>>(emb, attn_w, attn_b);
    hist_kernel<<<NUM_SPANS / 256, 256>>>(starts);
    scan_kernel<<<1, 1024>>>();
    scatter_kernel<<<NUM_SPANS / 256, 256>>>(starts);
    span_main<<<NUM_SPANS / SPB, 256>>>(emb, starts, ends, out);
}

// round 6
// speedup vs baseline: 1.5821x; 1.2446x over previous
#include <cuda_runtime.h>

#define SEQ_LEN   8192
#define HIDDEN    1024
#define H4        256                 // float4 per row
#define NUM_SPANS 4096
#define MAX_W     32
#define SPB       8                   // sorted spans per block

__device__ float g_scores[SEQ_LEN];
__device__ int   g_cnt[SEQ_LEN];
__device__ int   g_off[SEQ_LEN];
__device__ int   g_sorted[NUM_SPANS];

// ---------------- Kernel A: per-position logits + zero histogram ----------
__global__ void score_kernel(const float* __restrict__ emb,
                             const float* __restrict__ attn_w,
                             const float* __restrict__ attn_b) {
    int gtid = blockIdx.x * blockDim.x + threadIdx.x;
    if (gtid < SEQ_LEN) g_cnt[gtid] = 0;

    int warp = gtid >> 5;
    int lane = threadIdx.x & 31;
    if (warp >= SEQ_LEN) return;

    const float4* row = (const float4*)(emb) + (size_t)warp * H4;
    const float4* wv  = (const float4*)(attn_w);

    float acc = 0.0f;
#pragma unroll
    for (int j = 0; j < H4 / 32; j++) {
        float4 a = row[j * 32 + lane];
        float4 c = wv [j * 32 + lane];
        acc += a.x * c.x + a.y * c.y + a.z * c.z + a.w * c.w;
    }
#pragma unroll
    for (int off = 16; off; off >>= 1)
        acc += __shfl_xor_sync(0xffffffffu, acc, off);

    if (lane == 0) g_scores[warp] = acc + attn_b[0];
}

// ---------------- Kernel B: histogram of starts ---------------------------
__global__ void hist_kernel(const int* __restrict__ starts) {
    int j = blockIdx.x * blockDim.x + threadIdx.x;
    if (j < NUM_SPANS) atomicAdd(&g_cnt[starts[j]], 1);
}

// ---------------- Kernel C: exclusive scan of 8192 counters (1 block) -----
__global__ __launch_bounds__(1024) void scan_kernel() {
    __shared__ int wsum[32];
    const int t = threadIdx.x;            // 8 elems each
    const int base = t * 8;

    int loc[8];
    int run = 0;
#pragma unroll
    for (int i = 0; i < 8; i++) { loc[i] = run; run += g_cnt[base + i]; }

    const int lane = t & 31, wid = t >> 5;
    int x = run;
#pragma unroll
    for (int off = 1; off < 32; off <<= 1) {
        int y = __shfl_up_sync(0xffffffffu, x, off);
        if (lane >= off) x += y;
    }
    if (lane == 31) wsum[wid] = x;
    __syncthreads();
    if (wid == 0) {
        int s = wsum[lane];
#pragma unroll
        for (int off = 1; off < 32; off <<= 1) {
            int y = __shfl_up_sync(0xffffffffu, s, off);
            if (lane >= off) s += y;
        }
        wsum[lane] = s;
    }
    __syncthreads();

    int excl = x - run + (wid ? wsum[wid - 1] : 0);
#pragma unroll
    for (int i = 0; i < 8; i++) g_off[base + i] = excl + loc[i];
}

// ---------------- Kernel D: scatter span ids into sorted order ------------
__global__ void scatter_kernel(const int* __restrict__ starts) {
    int j = blockIdx.x * blockDim.x + threadIdx.x;
    if (j >= NUM_SPANS) return;
    int p = atomicAdd(&g_off[starts[j]], 1);
    g_sorted[p] = j;
}

// ---------------- Kernel E: main — 8 sorted spans/block, row-major --------
__global__ __launch_bounds__(256) void span_main(
        const float* __restrict__ emb,
        const int*   __restrict__ starts,
        const int*   __restrict__ ends,
        float*       __restrict__ out) {
    __shared__ float s_w[SPB][MAX_W];
    __shared__ int   s_s[SPB], s_e[SPB], s_j[SPB];

    const int tid  = threadIdx.x;         // 256 == H4: one float4 column
    const int wid  = tid >> 5;
    const int lane = tid & 31;

    // ---- warp w: softmax for slot w ----
    {
        int j = g_sorted[blockIdx.x * SPB + wid];
        int s = starts[j];
        int W = ends[j] - s;              // width-1 in [0,31]
        float sc = (lane <= W) ? g_scores[s + lane] : -1e9f;
        float m = sc;
#pragma unroll
        for (int off = 16; off; off >>= 1)
            m = fmaxf(m, __shfl_xor_sync(0xffffffffu, m, off));
        float p = __expf(sc - m);
        float sum = p;
#pragma unroll
        for (int off = 16; off; off >>= 1)
            sum += __shfl_xor_sync(0xffffffffu, sum, off);
        s_w[wid][lane] = p / sum;
        if (lane == 0) { s_s[wid] = s; s_e[wid] = s + W; s_j[wid] = j; }
    }
    __syncthreads();

    // span bounds into registers (broadcast LDS)
    int ss[SPB], se[SPB];
    size_t obase[SPB];
#pragma unroll
    for (int k = 0; k < SPB; k++) {
        ss[k] = s_s[k];
        se[k] = s_e[k];
        obase[k] = (size_t)s_j[k] * (3 * H4);
    }

    int rmin = ss[0];                      // sorted by start
    int rmax = se[0];
#pragma unroll
    for (int k = 1; k < SPB; k++) rmax = max(rmax, se[k]);

    float4 acc[SPB];
#pragma unroll
    for (int k = 0; k < SPB; k++) acc[k] = make_float4(0.f, 0.f, 0.f, 0.f);

    const float4* col = (const float4*)(emb) + tid;
    float4*       ob  = (float4*)(out) + tid;

    // ---- single pass over the union row window ----
#pragma unroll 2
    for (int r = rmin; r <= rmax; r++) {
        float4 v = col[(size_t)r * H4];    // one load, used by up to 8 spans
#pragma unroll
        for (int k = 0; k < SPB; k++) {
            int rel = r - ss[k];
            if ((unsigned)rel <= (unsigned)(se[k] - ss[k])) {
                float wgt = s_w[k][rel];
                acc[k].x = fmaf(wgt, v.x, acc[k].x);
                acc[k].y = fmaf(wgt, v.y, acc[k].y);
                acc[k].z = fmaf(wgt, v.z, acc[k].z);
                acc[k].w = fmaf(wgt, v.w, acc[k].w);
                if (rel == 0)   ob[obase[k]]      = v;   // start_emb
                if (r == se[k]) ob[obase[k] + H4] = v;   // end_emb
            }
        }
    }
#pragma unroll
    for (int k = 0; k < SPB; k++)
        ob[obase[k] + 2 * H4] = acc[k];                  // attn_out
}

extern "C" void kernel_launch(void* const* d_in, const int* in_sizes, int n_in,
                              void* d_out, int out_size) {
    const float* emb    = (const float*)d_in[0];
    const int*   starts = (const int*)  d_in[1];
    const int*   ends   = (const int*)  d_in[2];
    const float* attn_w = (const float*)d_in[3];
    const float* attn_b = (const float*)d_in[4];
    float*       out    = (float*)d_out;

    score_kernel<<<SEQ_LEN / 8, 256>>>(emb, attn_w, attn_b);
    hist_kernel<<<NUM_SPANS / 256, 256>>>(starts);
    scan_kernel<<<1, 1024>>>();
    scatter_kernel<<<NUM_SPANS / 256, 256>>>(starts);
    span_main<<<NUM_SPANS / SPB, 256>>>(emb, starts, ends, out);
}